// round 15
// baseline (speedup 1.0000x reference)
#include <cuda_runtime.h>
#include <cuda_bf16.h>
#include <math.h>
#include <stdint.h>

// Problem constants
#define HH      112
#define WW2     112
#define CC      96
#define SHIFT_  3
#define NTOK    49
#define QKSCALE 0.17677669529663687f
#define NWIN_TOT 16384
#define NBLK2    12544     // 802816 / 64

// ===========================================================================
// MMA / LDSM helpers
// ===========================================================================
__device__ __forceinline__ void mma16816(float d[4], const uint32_t a[4],
                                         uint32_t b0, uint32_t b1) {
    asm volatile(
        "mma.sync.aligned.m16n8k16.row.col.f32.bf16.bf16.f32 "
        "{%0,%1,%2,%3},{%4,%5,%6,%7},{%8,%9},{%0,%1,%2,%3};"
        : "+f"(d[0]), "+f"(d[1]), "+f"(d[2]), "+f"(d[3])
        : "r"(a[0]), "r"(a[1]), "r"(a[2]), "r"(a[3]), "r"(b0), "r"(b1));
}

__device__ __forceinline__ void ldsm4(uint32_t r[4], uint32_t saddr) {
    asm volatile("ldmatrix.sync.aligned.m8n8.x4.shared.b16 {%0,%1,%2,%3}, [%4];"
        : "=r"(r[0]), "=r"(r[1]), "=r"(r[2]), "=r"(r[3]) : "r"(saddr));
}

__device__ __forceinline__ void ldsm4t(uint32_t r[4], uint32_t saddr) {
    asm volatile("ldmatrix.sync.aligned.m8n8.x4.trans.shared.b16 {%0,%1,%2,%3}, [%4];"
        : "=r"(r[0]), "=r"(r[1]), "=r"(r[2]), "=r"(r[3]) : "r"(saddr));
}

__device__ __forceinline__ uint32_t cvsm(const void* p) {
    return (uint32_t)__cvta_generic_to_shared(p);
}

__device__ __forceinline__ uint32_t packbf(float x0, float x1) {
    uint32_t p;
    asm("cvt.rn.bf16x2.f32 %0, %1, %2;" : "=r"(p) : "f"(x1), "f"(x0));
    return p;
}

// streamed 16B load, evict-first (doesn't thrash weight lines in L1)
__device__ __forceinline__ uint4 ldg_ef_u128(const uint32_t* p) {
    uint4 v;
    asm("ld.global.L1::evict_first.v4.u32 {%0,%1,%2,%3}, [%4];"
        : "=r"(v.x), "=r"(v.y), "=r"(v.z), "=r"(v.w) : "l"(p));
    return v;
}

__device__ __forceinline__ float2 unpack_bf2(uint32_t w) {
    __nv_bfloat162 b = *reinterpret_cast<__nv_bfloat162*>(&w);
    return __bfloat1622float2(b);
}

// tanh-form GELU: x * sigmoid(1.5957691216x + 0.0713548162x^3)
__device__ __forceinline__ float gelu_fast(float x) {
    float x2 = x * x;
    float z2 = x * fmaf(0.0713548162f, x2, 1.5957691216f);
    return __fdividef(x, 1.0f + __expf(-z2));
}

// Pre-packed weights (bf16 hi only): [k16step s][n][q] -> uint2 (b0, b1)
__device__ uint2 g_W1h[6 * 384 * 4];
__device__ uint2 g_W2h[24 * 96 * 4];
__device__ uint2 g_Wqh[6 * 288 * 4];
__device__ uint2 g_Wph[6 * 96 * 4];
// fused rel-pos-bias + shift mask, bf16x2-packed, 64x64 padded with -1e4.
// Inner 32 words permuted for vector loads: word p = qd*8 + nt holds the
// bf16 pair for j = {8*nt + 2*qd, 8*nt + 2*qd + 1}.  [rem][h][i][p<32]
__device__ uint32_t g_bm2[256 * 3 * 64 * 32];

__global__ void pack_weights(const float* __restrict__ fc1_w,
                             const float* __restrict__ fc2_w,
                             const float* __restrict__ qkv_w,
                             const float* __restrict__ proj_w) {
    int idx = blockIdx.x * 256 + threadIdx.x;
    if (idx >= 9216) return;
    {   // fc1: 96 x 384
        int q = idx & 3, n = (idx >> 2) % 384, s = idx / 1536;
        int k = s * 16 + 2 * q;
        g_W1h[idx] = make_uint2(
            packbf(fc1_w[k * 384 + n],       fc1_w[(k + 1) * 384 + n]),
            packbf(fc1_w[(k + 8) * 384 + n], fc1_w[(k + 9) * 384 + n]));
    }
    {   // fc2: 384 x 96
        int q = idx & 3, n = (idx >> 2) % 96, s = idx / 384;
        int k = s * 16 + 2 * q;
        g_W2h[idx] = make_uint2(
            packbf(fc2_w[k * 96 + n],       fc2_w[(k + 1) * 96 + n]),
            packbf(fc2_w[(k + 8) * 96 + n], fc2_w[(k + 9) * 96 + n]));
    }
    if (idx < 6912) {   // qkv: 96 x 288 (q cols pre-scaled)
        int q = idx & 3, n = (idx >> 2) % 288, s = idx / 1152;
        int k = s * 16 + 2 * q;
        float sc = (n < 96) ? QKSCALE : 1.0f;
        g_Wqh[idx] = make_uint2(
            packbf(qkv_w[k * 288 + n] * sc,       qkv_w[(k + 1) * 288 + n] * sc),
            packbf(qkv_w[(k + 8) * 288 + n] * sc, qkv_w[(k + 9) * 288 + n] * sc));
    }
    if (idx < 2304) {   // proj: 96 x 96
        int q = idx & 3, n = (idx >> 2) % 96, s = idx / 384;
        int k = s * 16 + 2 * q;
        g_Wph[idx] = make_uint2(
            packbf(proj_w[k * 96 + n],       proj_w[(k + 1) * 96 + n]),
            packbf(proj_w[(k + 8) * 96 + n], proj_w[(k + 9) * 96 + n]));
    }
}

// bias+mask builder -> bf16x2 packed, permuted inner order (word p=qd*8+nt)
__global__ void build_bias_mask(const float* __restrict__ rpb,
                                const int* __restrict__ relidx,
                                const float* __restrict__ amask) {
    int idx = blockIdx.x * 256 + threadIdx.x;   // < 256*3*64*16
    int w2  = idx & 15;                          // handles words 2*w2, 2*w2+1
    int i   = (idx >> 4) & 63;
    int h   = (idx >> 10) % 3;
    int rem = idx / 3072;
    const float* am = amask + (size_t)rem * 2401 + i * NTOK;
    const int*   ri = relidx + i * NTOK;
    #pragma unroll
    for (int e = 0; e < 2; ++e) {
        int p  = 2*w2 + e;
        int qd = p >> 3, nt = p & 7;
        int j0 = 8*nt + 2*qd;
        float v0 = -10000.0f, v1 = -10000.0f;
        if (i < NTOK) {
            if (j0     < NTOK) v0 = rpb[ri[j0]     * 3 + h] + am[j0];
            if (j0 + 1 < NTOK) v1 = rpb[ri[j0 + 1] * 3 + h] + am[j0 + 1];
        }
        g_bm2[idx*2 + e] = packbf(v0, v1);
    }
}

// ---------------------------------------------------------------------------
// Kernel 1: LN1 + shifted-window MHSA + proj + residual.
// One block per window (49 tokens -> 64), 256 threads (8 warps), 2 blocks/SM.
// Fused softmax+AV: probs never touch smem (score C-frag == AV A-frag layout).
// smem bytes:
//   [0, 13312)        xlnHi[64][104]   (dead after phase 1)
//   [13312, 26624)    qHi[64][104]     -> later aoHi
//   [26624, 39936)    kHi[64][104]
//   [39936, 53248)    vHi[64][104]     (token-major)
//   [53248, 53444)    srcI[49]
// ---------------------------------------------------------------------------
#define SM_Q    13312
#define SM_K    26624
#define SM_V    39936
#define SM_SRC  53248
#define SMEM1   53504

__global__ __launch_bounds__(256, 2)
void swin_attn_mma(const float* __restrict__ x,
                   const float* __restrict__ g1, const float* __restrict__ b1,
                   const float* __restrict__ qkv_b,
                   const float* __restrict__ proj_b,
                   float* __restrict__ out)
{
    extern __shared__ char sm[];
    __nv_bfloat16* xlnHi = (__nv_bfloat16*)(sm);
    uint32_t* qh32 = (uint32_t*)(sm + SM_Q);
    uint32_t* kh32 = (uint32_t*)(sm + SM_K);
    uint32_t* vh32 = (uint32_t*)(sm + SM_V);
    uint32_t* aoh32 = qh32;                     // alias q (per-unit disjoint)
    int* srcI = (int*)(sm + SM_SRC);

    const uint32_t smb = cvsm(sm);
    const int tid  = threadIdx.x;
    const int warp = tid >> 5, lane = tid & 31;
    const int r    = lane >> 2;
    const int qd   = lane & 3;
    const int c2   = qd * 2;
    const int la15 = lane & 15;
    const int kadj = (lane >> 4) << 3;
    const int lbn  = (lane & 7) | ((lane >> 4) << 3);
    const int kbdj = ((lane >> 3) & 1) << 3;
    const int w    = blockIdx.x;
    const int bimg = w >> 8;
    const int rem  = w & 255;
    const int wh   = rem >> 4, wwc = rem & 15;

    // ---- Phase 0: LN + shifted gather -> xln bf16 ----
    {
        float ga = g1[lane], gb = g1[lane+32], gc = g1[lane+64];
        float ba = b1[lane], bb = b1[lane+32], bc = b1[lane+64];
        for (int t = warp; t < NTOK; t += 8) {
            int ii = t / 7, jj = t - ii*7;
            int oh = wh*7 + ii + SHIFT_; if (oh >= HH)  oh -= HH;
            int ow = wwc*7 + jj + SHIFT_; if (ow >= WW2) ow -= WW2;
            int src = (bimg*HH + oh)*WW2 + ow;
            if (lane == 0) srcI[t] = src;
            const float* xr = x + (size_t)src*CC;
            float v0 = xr[lane], v1 = xr[lane+32], v2 = xr[lane+64];
            float s = v0 + v1 + v2;
            #pragma unroll
            for (int o = 16; o; o >>= 1) s += __shfl_xor_sync(0xffffffffu, s, o);
            float mean = s * (1.0f/96.0f);
            float d0 = v0-mean, d1 = v1-mean, d2 = v2-mean;
            float q2 = d0*d0 + d1*d1 + d2*d2;
            #pragma unroll
            for (int o = 16; o; o >>= 1) q2 += __shfl_xor_sync(0xffffffffu, q2, o);
            float rstd = rsqrtf(q2*(1.0f/96.0f) + 1e-5f);
            xlnHi[t*104 + lane]    = __float2bfloat16_rn(d0*rstd*ga + ba);
            xlnHi[t*104 + lane+32] = __float2bfloat16_rn(d1*rstd*gb + bb);
            xlnHi[t*104 + lane+64] = __float2bfloat16_rn(d2*rstd*gc + bc);
        }
        __nv_bfloat16 z = __float2bfloat16_rn(0.0f);
        for (int idx = tid; idx < 15*96; idx += 256) {
            int rr = NTOK + idx/96, cc = idx - (idx/96)*96;
            xlnHi[rr*104 + cc] = z;
        }
    }
    __syncthreads();

    // ---- Phase 1: QKV GEMM (M=64, K=96, N=288), single bf16 MMA ----
    {
        const int wm = warp >> 2, wn = warp & 3;
        const uint32_t aHi = smb + (wm*32 + la15)*208 + kadj*2;
        for (int g = 0; g < 3; ++g) {
            float acc[3][2][4];
            #pragma unroll
            for (int a = 0; a < 3; ++a)
                #pragma unroll
                for (int b = 0; b < 2; ++b)
                    #pragma unroll
                    for (int c = 0; c < 4; ++c) acc[a][b][c] = 0.f;
            #pragma unroll
            for (int s = 0; s < 6; ++s) {
                uint32_t ah[2][4];
                ldsm4(ah[0], aHi + s*32);
                ldsm4(ah[1], aHi + 3328 + s*32);
                #pragma unroll
                for (int nt = 0; nt < 3; ++nt) {
                    int n = wn*72 + g*24 + nt*8 + r;
                    uint2 B = g_Wqh[(s*288 + n)*4 + qd];
                    #pragma unroll
                    for (int mt = 0; mt < 2; ++mt)
                        mma16816(acc[nt][mt], ah[mt], B.x, B.y);
                }
            }
            // epilogue: +bias, route to qHi / kHi / vHi (token-major)
            #pragma unroll
            for (int nt = 0; nt < 3; ++nt) {
                int nb = wn*72 + g*24 + nt*8 + c2;
                float b0v = qkv_b[nb], b1v = qkv_b[nb+1];
                if (nb < 96) { b0v *= QKSCALE; b1v *= QKSCALE; }
                #pragma unroll
                for (int mt = 0; mt < 2; ++mt) {
                    int row = wm*32 + mt*16 + r;
                    float v00 = acc[nt][mt][0] + b0v, v01 = acc[nt][mt][1] + b1v;
                    float v10 = acc[nt][mt][2] + b0v, v11 = acc[nt][mt][3] + b1v;
                    uint32_t* dst;
                    int c;
                    if (nb < 96)       { dst = qh32; c = nb; }
                    else if (nb < 192) { dst = kh32; c = nb - 96; }
                    else               { dst = vh32; c = nb - 192; }
                    dst[(row*104 + c) >> 1]     = packbf(v00, v01);
                    dst[((row+8)*104 + c) >> 1] = packbf(v10, v11);
                }
            }
        }
    }
    __syncthreads();

    // ---- Phase 2+3 fused: scores + bias/mask + softmax + A.V, probs in regs.
    for (int u = warp; u < 12; u += 8) {
        int h = u >> 2, mt = u & 3;
        int rowb = mt * 16;
        uint32_t a[4];
        ldsm4(a, smb + SM_Q + (rowb + la15)*208 + (h*32 + kadj)*2);
        float acc[8][4];
        #pragma unroll
        for (int aa = 0; aa < 8; ++aa)
            #pragma unroll
            for (int c = 0; c < 4; ++c) acc[aa][c] = 0.f;
        const uint32_t kb = smb + SM_K + lbn*208 + (h*32 + kbdj)*2;
        #pragma unroll
        for (int p = 0; p < 4; ++p) {
            uint32_t b[4];
            ldsm4(b, kb + p*16*208);
            mma16816(acc[2*p],   a, b[0], b[1]);
            mma16816(acc[2*p+1], a, b[2], b[3]);
        }
        // bias/mask via 16B vector loads (permuted layout: word p = qd*8+nt)
        const uint32_t* bmb = g_bm2 + ((size_t)(rem*3 + h)) * 2048;
        int i0 = rowb + r, i1 = i0 + 8;
        const uint32_t* p0 = bmb + i0*32 + qd*8;
        const uint32_t* p1 = bmb + i1*32 + qd*8;
        uint4 A0a = ldg_ef_u128(p0), A0b = ldg_ef_u128(p0 + 4);
        uint4 A1a = ldg_ef_u128(p1), A1b = ldg_ef_u128(p1 + 4);
        uint32_t w0[8] = {A0a.x, A0a.y, A0a.z, A0a.w, A0b.x, A0b.y, A0b.z, A0b.w};
        uint32_t w1[8] = {A1a.x, A1a.y, A1a.z, A1a.w, A1b.x, A1b.y, A1b.z, A1b.w};
        float s0 = 0.f, s1 = 0.f;
        #pragma unroll
        for (int nt = 0; nt < 8; ++nt) {
            float2 bm0 = unpack_bf2(w0[nt]);
            float2 bm1 = unpack_bf2(w1[nt]);
            acc[nt][0] = __expf(acc[nt][0] + bm0.x);
            acc[nt][1] = __expf(acc[nt][1] + bm0.y);
            acc[nt][2] = __expf(acc[nt][2] + bm1.x);
            acc[nt][3] = __expf(acc[nt][3] + bm1.y);
            s0 += acc[nt][0] + acc[nt][1];
            s1 += acc[nt][2] + acc[nt][3];
        }
        s0 += __shfl_xor_sync(0xffffffffu, s0, 1);
        s0 += __shfl_xor_sync(0xffffffffu, s0, 2);
        s1 += __shfl_xor_sync(0xffffffffu, s1, 1);
        s1 += __shfl_xor_sync(0xffffffffu, s1, 2);
        float inv0 = 1.0f / s0, inv1 = 1.0f / s1;
        // probs -> bf16 A-fragments directly in registers
        uint32_t pa[4][4];
        #pragma unroll
        for (int ks = 0; ks < 4; ++ks) {
            pa[ks][0] = packbf(acc[2*ks][0]*inv0,   acc[2*ks][1]*inv0);
            pa[ks][1] = packbf(acc[2*ks][2]*inv1,   acc[2*ks][3]*inv1);
            pa[ks][2] = packbf(acc[2*ks+1][0]*inv0, acc[2*ks+1][1]*inv0);
            pa[ks][3] = packbf(acc[2*ks+1][2]*inv1, acc[2*ks+1][3]*inv1);
        }
        // A.V: 16 rows x 32 channels of head h
        float acc3[4][4];
        #pragma unroll
        for (int aa = 0; aa < 4; ++aa)
            #pragma unroll
            for (int c = 0; c < 4; ++c) acc3[aa][c] = 0.f;
        const uint32_t v_b = smb + SM_V + la15*208 + (h*32 + kadj)*2;
        #pragma unroll
        for (int ks = 0; ks < 4; ++ks) {
            uint32_t bh0[4], bh1[4];
            ldsm4t(bh0, v_b + ks*16*208);
            ldsm4t(bh1, v_b + ks*16*208 + 32);
            mma16816(acc3[0], pa[ks], bh0[0], bh0[1]);
            mma16816(acc3[1], pa[ks], bh0[2], bh0[3]);
            mma16816(acc3[2], pa[ks], bh1[0], bh1[1]);
            mma16816(acc3[3], pa[ks], bh1[2], bh1[3]);
        }
        // write ao tile (aliases q; disjoint per unit)
        #pragma unroll
        for (int nt = 0; nt < 4; ++nt) {
            int c = h*32 + nt*8 + c2;
            aoh32[(i0*104 + c) >> 1] = packbf(acc3[nt][0], acc3[nt][1]);
            aoh32[(i1*104 + c) >> 1] = packbf(acc3[nt][2], acc3[nt][3]);
        }
    }
    __syncthreads();

    // ---- Phase 4: proj + bias + residual -> gmem ----
    {
        const int wm = warp >> 2, wn = warp & 3;
        const uint32_t aHi = smb + SM_Q + (wm*32 + la15)*208 + kadj*2;
        float acc[3][2][4];
        #pragma unroll
        for (int a = 0; a < 3; ++a)
            #pragma unroll
            for (int b = 0; b < 2; ++b)
                #pragma unroll
                for (int c = 0; c < 4; ++c) acc[a][b][c] = 0.f;
        #pragma unroll
        for (int s = 0; s < 6; ++s) {
            uint32_t ah[2][4];
            ldsm4(ah[0], aHi + s*32);
            ldsm4(ah[1], aHi + 3328 + s*32);
            #pragma unroll
            for (int nt = 0; nt < 3; ++nt) {
                int n = wn*24 + nt*8 + r;
                uint2 B = g_Wph[(s*96 + n)*4 + qd];
                #pragma unroll
                for (int mt = 0; mt < 2; ++mt)
                    mma16816(acc[nt][mt], ah[mt], B.x, B.y);
            }
        }
        #pragma unroll
        for (int nt = 0; nt < 3; ++nt) {
            int c = wn*24 + nt*8 + c2;
            float2 pb = *(const float2*)(proj_b + c);
            #pragma unroll
            for (int mt = 0; mt < 2; ++mt) {
                int i0 = wm*32 + mt*16 + r;
                if (i0 < NTOK) {
                    size_t base = (size_t)srcI[i0]*96 + c;
                    float2 xr = *(const float2*)(x + base);
                    float2 o;
                    o.x = acc[nt][mt][0] + pb.x + xr.x;
                    o.y = acc[nt][mt][1] + pb.y + xr.y;
                    *(float2*)(out + base) = o;
                }
                int i1 = i0 + 8;
                if (i1 < NTOK) {
                    size_t base = (size_t)srcI[i1]*96 + c;
                    float2 xr = *(const float2*)(x + base);
                    float2 o;
                    o.x = acc[nt][mt][2] + pb.x + xr.x;
                    o.y = acc[nt][mt][3] + pb.y + xr.y;
                    *(float2*)(out + base) = o;
                }
            }
        }
    }
}

// ---------------------------------------------------------------------------
// Kernel 2: LN2 + MLP, 64 tokens/block, 256 threads (8 warps), 2 blocks/SM.
// EXACT R12/R13/R14 version (fast tanh-GELU, uint2 coalesced weights).
// smem: xhi[64][104] @0 (13312), hhi[64][136] @13312 (17408) = 30720 B.
// ---------------------------------------------------------------------------
#define XLDA 104
#define HLDA 136
#define SM2_H 13312
#define SMEM2 30720

__global__ __launch_bounds__(256, 2)
void swin_mlp_mma(const float* __restrict__ g2, const float* __restrict__ b2,
                  const float* __restrict__ fc1_b, const float* __restrict__ fc2_b,
                  float* __restrict__ xio)
{
    extern __shared__ char smem_raw[];
    __nv_bfloat16* xhi = (__nv_bfloat16*)smem_raw;
    uint32_t* hhi32 = (uint32_t*)(smem_raw + SM2_H);

    const uint32_t smb = cvsm(smem_raw);
    const int tid   = threadIdx.x;
    const int warp  = tid >> 5, lane = tid & 31;
    const int tok0  = blockIdx.x * 64;
    const int r     = lane >> 2;
    const int c2    = (lane & 3) * 2;
    const int q     = lane & 3;
    const int nlane = lane >> 2;
    const int la15  = lane & 15;
    const int kadj  = (lane >> 4) << 3;

    // ---- LN2 -> bf16 A matrix in smem ----
    {
        float ga = g2[lane], gb = g2[lane+32], gc = g2[lane+64];
        float ba = b2[lane], bb = b2[lane+32], bc = b2[lane+64];
        for (int t = warp; t < 64; t += 8) {
            const float* xr = xio + (size_t)(tok0+t)*96;
            float v0 = xr[lane], v1 = xr[lane+32], v2 = xr[lane+64];
            float s = v0 + v1 + v2;
            #pragma unroll
            for (int o = 16; o; o >>= 1) s += __shfl_xor_sync(0xffffffffu, s, o);
            float mean = s * (1.0f/96.0f);
            float d0 = v0-mean, d1 = v1-mean, d2 = v2-mean;
            float q2 = d0*d0 + d1*d1 + d2*d2;
            #pragma unroll
            for (int o = 16; o; o >>= 1) q2 += __shfl_xor_sync(0xffffffffu, q2, o);
            float rstd = rsqrtf(q2*(1.0f/96.0f) + 1e-5f);
            xhi[t*XLDA + lane]      = __float2bfloat16_rn(d0*rstd*ga + ba);
            xhi[t*XLDA + lane + 32] = __float2bfloat16_rn(d1*rstd*gb + bb);
            xhi[t*XLDA + lane + 64] = __float2bfloat16_rn(d2*rstd*gc + bc);
        }
    }
    __syncthreads();

    float acc2[6][4];
    #pragma unroll
    for (int i = 0; i < 6; ++i)
        #pragma unroll
        for (int j = 0; j < 4; ++j) acc2[i][j] = 0.f;

    const int wm1 = warp >> 2, wn1 = warp & 3;
    const int wm2 = warp >> 1, wn2 = warp & 1;

    const uint32_t aX = smb + (wm1*32 + la15)*208 + kadj*2;
    const uint32_t aH = smb + SM2_H + (wm2*16 + la15)*272 + kadj*2;

    for (int ch = 0; ch < 3; ++ch) {
        // ---- GEMM1: x(64x96) @ W1[:, ch*128 : +128] ----
        float acc1[2][4][4];
        #pragma unroll
        for (int a = 0; a < 2; ++a)
            #pragma unroll
            for (int b = 0; b < 4; ++b)
                #pragma unroll
                for (int c = 0; c < 4; ++c) acc1[a][b][c] = 0.f;

        #pragma unroll
        for (int s = 0; s < 6; ++s) {
            uint32_t ah[2][4];
            ldsm4(ah[0], aX + s*32);
            ldsm4(ah[1], aX + 3328 + s*32);
            #pragma unroll
            for (int nt = 0; nt < 4; ++nt) {
                int n = ch*128 + wn1*32 + nt*8 + nlane;
                uint2 B = g_W1h[(s*384 + n)*4 + q];
                #pragma unroll
                for (int mt = 0; mt < 2; ++mt)
                    mma16816(acc1[mt][nt], ah[mt], B.x, B.y);
            }
        }

        __syncthreads();   // previous chunk's GEMM2 reads of h are done

        // ---- bias + fast GELU -> h smem (bf16) ----
        #pragma unroll
        for (int mt = 0; mt < 2; ++mt) {
            int row0 = wm1*32 + mt*16 + r;
            #pragma unroll
            for (int nt = 0; nt < 4; ++nt) {
                int cc = wn1*32 + nt*8 + c2;
                float2 bia = *(const float2*)(fc1_b + ch*128 + cc);
                float g00 = gelu_fast(acc1[mt][nt][0] + bia.x);
                float g01 = gelu_fast(acc1[mt][nt][1] + bia.y);
                hhi32[(row0*HLDA + cc) >> 1] = packbf(g00, g01);
                float g10 = gelu_fast(acc1[mt][nt][2] + bia.x);
                float g11 = gelu_fast(acc1[mt][nt][3] + bia.y);
                hhi32[((row0+8)*HLDA + cc) >> 1] = packbf(g10, g11);
            }
        }
        __syncthreads();

        // ---- GEMM2 partial: acc2 += h_chunk(64x128) @ W2[chunk, :] ----
        #pragma unroll
        for (int s = 0; s < 8; ++s) {
            uint32_t ah[4];
            ldsm4(ah, aH + s*32);
            const int S = ch*8 + s;
            #pragma unroll
            for (int nt = 0; nt < 6; ++nt) {
                int n = wn2*48 + nt*8 + nlane;
                uint2 B = g_W2h[(S*96 + n)*4 + q];
                mma16816(acc2[nt], ah, B.x, B.y);
            }
        }
    }

    // ---- epilogue: bias + residual, in place ----
    {
        const int m0 = wm2*16;
        #pragma unroll
        for (int nt = 0; nt < 6; ++nt) {
            int cg = wn2*48 + nt*8 + c2;
            float2 bia = *(const float2*)(fc2_b + cg);
            size_t b0 = (size_t)(tok0 + m0 + r)*96 + cg;
            float2 sk0 = *(const float2*)(xio + b0);
            float2 o0;
            o0.x = acc2[nt][0] + bia.x + sk0.x;
            o0.y = acc2[nt][1] + bia.y + sk0.y;
            *(float2*)(xio + b0) = o0;
            size_t b1 = b0 + (size_t)8*96;
            float2 sk1 = *(const float2*)(xio + b1);
            float2 o1;
            o1.x = acc2[nt][2] + bia.x + sk1.x;
            o1.y = acc2[nt][3] + bia.y + sk1.y;
            *(float2*)(xio + b1) = o1;
        }
    }
}

// ---------------------------------------------------------------------------
extern "C" void kernel_launch(void* const* d_in, const int* in_sizes, int n_in,
                              void* d_out, int out_size)
{
    const float* x      = (const float*)d_in[0];
    const float* g1     = (const float*)d_in[1];
    const float* b1     = (const float*)d_in[2];
    const float* qkv_w  = (const float*)d_in[3];
    const float* qkv_b  = (const float*)d_in[4];
    const float* proj_w = (const float*)d_in[5];
    const float* proj_b = (const float*)d_in[6];
    const float* rpb    = (const float*)d_in[7];
    const float* g2     = (const float*)d_in[8];
    const float* b2     = (const float*)d_in[9];
    const float* fc1_w  = (const float*)d_in[10];
    const float* fc1_b  = (const float*)d_in[11];
    const float* fc2_w  = (const float*)d_in[12];
    const float* fc2_b  = (const float*)d_in[13];
    const int*   relidx = (const int*)d_in[14];
    const float* amask  = (const float*)d_in[15];
    float* out = (float*)d_out;

    cudaFuncSetAttribute(swin_attn_mma, cudaFuncAttributeMaxDynamicSharedMemorySize, SMEM1);
    cudaFuncSetAttribute(swin_mlp_mma,  cudaFuncAttributeMaxDynamicSharedMemorySize, SMEM2);

    pack_weights<<<36, 256>>>(fc1_w, fc2_w, qkv_w, proj_w);
    build_bias_mask<<<3072, 256>>>(rpb, relidx, amask);
    swin_attn_mma<<<NWIN_TOT, 256, SMEM1>>>(x, g1, b1, qkv_b, proj_b, out);
    swin_mlp_mma<<<NBLK2, 256, SMEM2>>>(g2, b2, fc1_b, fc2_b, out);
}

// round 16
// speedup vs baseline: 1.2488x; 1.2488x over previous
#include <cuda_runtime.h>
#include <cuda_bf16.h>
#include <math.h>
#include <stdint.h>

// Problem constants
#define HH      112
#define WW2     112
#define CC      96
#define SHIFT_  3
#define NTOK    49
#define QKSCALE 0.17677669529663687f
#define NWIN_TOT 16384
#define NBLK2    12544     // 802816 / 64

// ===========================================================================
// MMA / LDSM helpers
// ===========================================================================
__device__ __forceinline__ void mma16816(float d[4], const uint32_t a[4],
                                         uint32_t b0, uint32_t b1) {
    asm volatile(
        "mma.sync.aligned.m16n8k16.row.col.f32.bf16.bf16.f32 "
        "{%0,%1,%2,%3},{%4,%5,%6,%7},{%8,%9},{%0,%1,%2,%3};"
        : "+f"(d[0]), "+f"(d[1]), "+f"(d[2]), "+f"(d[3])
        : "r"(a[0]), "r"(a[1]), "r"(a[2]), "r"(a[3]), "r"(b0), "r"(b1));
}

__device__ __forceinline__ void ldsm4(uint32_t r[4], uint32_t saddr) {
    asm volatile("ldmatrix.sync.aligned.m8n8.x4.shared.b16 {%0,%1,%2,%3}, [%4];"
        : "=r"(r[0]), "=r"(r[1]), "=r"(r[2]), "=r"(r[3]) : "r"(saddr));
}

__device__ __forceinline__ void ldsm4t(uint32_t r[4], uint32_t saddr) {
    asm volatile("ldmatrix.sync.aligned.m8n8.x4.trans.shared.b16 {%0,%1,%2,%3}, [%4];"
        : "=r"(r[0]), "=r"(r[1]), "=r"(r[2]), "=r"(r[3]) : "r"(saddr));
}

__device__ __forceinline__ uint32_t cvsm(const void* p) {
    return (uint32_t)__cvta_generic_to_shared(p);
}

__device__ __forceinline__ uint32_t packbf(float x0, float x1) {
    uint32_t p;
    asm("cvt.rn.bf16x2.f32 %0, %1, %2;" : "=r"(p) : "f"(x1), "f"(x0));
    return p;
}

// streamed 16B load, evict-first (doesn't thrash weight lines in L1)
__device__ __forceinline__ uint4 ldg_ef_u128(const uint32_t* p) {
    uint4 v;
    asm("ld.global.L1::evict_first.v4.u32 {%0,%1,%2,%3}, [%4];"
        : "=r"(v.x), "=r"(v.y), "=r"(v.z), "=r"(v.w) : "l"(p));
    return v;
}

__device__ __forceinline__ float2 unpack_bf2(uint32_t w) {
    __nv_bfloat162 b = *reinterpret_cast<__nv_bfloat162*>(&w);
    return __bfloat1622float2(b);
}

// tanh-form GELU: x * sigmoid(1.5957691216x + 0.0713548162x^3)
__device__ __forceinline__ float gelu_fast(float x) {
    float x2 = x * x;
    float z2 = x * fmaf(0.0713548162f, x2, 1.5957691216f);
    return __fdividef(x, 1.0f + __expf(-z2));
}

// Pre-packed weights (bf16 hi only): [k16step s][n][q] -> uint2 (b0, b1)
__device__ uint2 g_W1h[6 * 384 * 4];
__device__ uint2 g_W2h[24 * 96 * 4];
__device__ uint2 g_Wqh[6 * 288 * 4];
__device__ uint2 g_Wph[6 * 96 * 4];
// fused rel-pos-bias + shift mask, bf16x2-packed, 64x64 padded with -1e4.
// Inner 32 words permuted for vector loads: word p = qd*8 + nt holds the
// bf16 pair for j = {8*nt + 2*qd, 8*nt + 2*qd + 1}.  [rem][h][i][p<32]
__device__ uint32_t g_bm2[256 * 3 * 64 * 32];

__global__ void pack_weights(const float* __restrict__ fc1_w,
                             const float* __restrict__ fc2_w,
                             const float* __restrict__ qkv_w,
                             const float* __restrict__ proj_w) {
    int idx = blockIdx.x * 256 + threadIdx.x;
    if (idx >= 9216) return;
    {   // fc1: 96 x 384
        int q = idx & 3, n = (idx >> 2) % 384, s = idx / 1536;
        int k = s * 16 + 2 * q;
        g_W1h[idx] = make_uint2(
            packbf(fc1_w[k * 384 + n],       fc1_w[(k + 1) * 384 + n]),
            packbf(fc1_w[(k + 8) * 384 + n], fc1_w[(k + 9) * 384 + n]));
    }
    {   // fc2: 384 x 96
        int q = idx & 3, n = (idx >> 2) % 96, s = idx / 384;
        int k = s * 16 + 2 * q;
        g_W2h[idx] = make_uint2(
            packbf(fc2_w[k * 96 + n],       fc2_w[(k + 1) * 96 + n]),
            packbf(fc2_w[(k + 8) * 96 + n], fc2_w[(k + 9) * 96 + n]));
    }
    if (idx < 6912) {   // qkv: 96 x 288 (q cols pre-scaled)
        int q = idx & 3, n = (idx >> 2) % 288, s = idx / 1152;
        int k = s * 16 + 2 * q;
        float sc = (n < 96) ? QKSCALE : 1.0f;
        g_Wqh[idx] = make_uint2(
            packbf(qkv_w[k * 288 + n] * sc,       qkv_w[(k + 1) * 288 + n] * sc),
            packbf(qkv_w[(k + 8) * 288 + n] * sc, qkv_w[(k + 9) * 288 + n] * sc));
    }
    if (idx < 2304) {   // proj: 96 x 96
        int q = idx & 3, n = (idx >> 2) % 96, s = idx / 384;
        int k = s * 16 + 2 * q;
        g_Wph[idx] = make_uint2(
            packbf(proj_w[k * 96 + n],       proj_w[(k + 1) * 96 + n]),
            packbf(proj_w[(k + 8) * 96 + n], proj_w[(k + 9) * 96 + n]));
    }
}

// bias+mask builder -> bf16x2 packed, permuted inner order (word p=qd*8+nt)
__global__ void build_bias_mask(const float* __restrict__ rpb,
                                const int* __restrict__ relidx,
                                const float* __restrict__ amask) {
    int idx = blockIdx.x * 256 + threadIdx.x;   // < 256*3*64*16
    int w2  = idx & 15;                          // handles words 2*w2, 2*w2+1
    int i   = (idx >> 4) & 63;
    int h   = (idx >> 10) % 3;
    int rem = idx / 3072;
    const float* am = amask + (size_t)rem * 2401 + i * NTOK;
    const int*   ri = relidx + i * NTOK;
    #pragma unroll
    for (int e = 0; e < 2; ++e) {
        int p  = 2*w2 + e;
        int qd = p >> 3, nt = p & 7;
        int j0 = 8*nt + 2*qd;
        float v0 = -10000.0f, v1 = -10000.0f;
        if (i < NTOK) {
            if (j0     < NTOK) v0 = rpb[ri[j0]     * 3 + h] + am[j0];
            if (j0 + 1 < NTOK) v1 = rpb[ri[j0 + 1] * 3 + h] + am[j0 + 1];
        }
        g_bm2[idx*2 + e] = packbf(v0, v1);
    }
}

// ---------------------------------------------------------------------------
// Kernel 1: LN1 + shifted-window MHSA + proj + residual.
// One block per window (49 tokens -> 64), 256 threads (8 warps), 2 blocks/SM.
// Fused softmax+AV: probs never touch smem (score C-frag == AV A-frag layout).
// smem bytes:
//   [0, 13312)        xlnHi[64][104]   (dead after phase 1)
//   [13312, 26624)    qHi[64][104]     -> later aoHi
//   [26624, 39936)    kHi[64][104]
//   [39936, 53248)    vHi[64][104]     (token-major)
//   [53248, 53444)    srcI[49]
// ---------------------------------------------------------------------------
#define SM_Q    13312
#define SM_K    26624
#define SM_V    39936
#define SM_SRC  53248
#define SMEM1   53504

__global__ __launch_bounds__(256, 2)
void swin_attn_mma(const float* __restrict__ x,
                   const float* __restrict__ g1, const float* __restrict__ b1,
                   const float* __restrict__ qkv_b,
                   const float* __restrict__ proj_b,
                   float* __restrict__ out)
{
    extern __shared__ char sm[];
    __nv_bfloat16* xlnHi = (__nv_bfloat16*)(sm);
    uint32_t* qh32 = (uint32_t*)(sm + SM_Q);
    uint32_t* kh32 = (uint32_t*)(sm + SM_K);
    uint32_t* vh32 = (uint32_t*)(sm + SM_V);
    uint32_t* aoh32 = qh32;                     // alias q (per-unit disjoint)
    int* srcI = (int*)(sm + SM_SRC);

    const uint32_t smb = cvsm(sm);
    const int tid  = threadIdx.x;
    const int warp = tid >> 5, lane = tid & 31;
    const int r    = lane >> 2;
    const int qd   = lane & 3;
    const int c2   = qd * 2;
    const int la15 = lane & 15;
    const int kadj = (lane >> 4) << 3;
    const int lbn  = (lane & 7) | ((lane >> 4) << 3);
    const int kbdj = ((lane >> 3) & 1) << 3;
    const int w    = blockIdx.x;
    const int bimg = w >> 8;
    const int rem  = w & 255;
    const int wh   = rem >> 4, wwc = rem & 15;

    // ---- Phase 0: LN + shifted gather -> xln bf16 ----
    {
        float ga = g1[lane], gb = g1[lane+32], gc = g1[lane+64];
        float ba = b1[lane], bb = b1[lane+32], bc = b1[lane+64];
        for (int t = warp; t < NTOK; t += 8) {
            int ii = t / 7, jj = t - ii*7;
            int oh = wh*7 + ii + SHIFT_; if (oh >= HH)  oh -= HH;
            int ow = wwc*7 + jj + SHIFT_; if (ow >= WW2) ow -= WW2;
            int src = (bimg*HH + oh)*WW2 + ow;
            if (lane == 0) srcI[t] = src;
            const float* xr = x + (size_t)src*CC;
            float v0 = xr[lane], v1 = xr[lane+32], v2 = xr[lane+64];
            float s = v0 + v1 + v2;
            #pragma unroll
            for (int o = 16; o; o >>= 1) s += __shfl_xor_sync(0xffffffffu, s, o);
            float mean = s * (1.0f/96.0f);
            float d0 = v0-mean, d1 = v1-mean, d2 = v2-mean;
            float q2 = d0*d0 + d1*d1 + d2*d2;
            #pragma unroll
            for (int o = 16; o; o >>= 1) q2 += __shfl_xor_sync(0xffffffffu, q2, o);
            float rstd = rsqrtf(q2*(1.0f/96.0f) + 1e-5f);
            xlnHi[t*104 + lane]    = __float2bfloat16_rn(d0*rstd*ga + ba);
            xlnHi[t*104 + lane+32] = __float2bfloat16_rn(d1*rstd*gb + bb);
            xlnHi[t*104 + lane+64] = __float2bfloat16_rn(d2*rstd*gc + bc);
        }
        __nv_bfloat16 z = __float2bfloat16_rn(0.0f);
        for (int idx = tid; idx < 15*96; idx += 256) {
            int rr = NTOK + idx/96, cc = idx - (idx/96)*96;
            xlnHi[rr*104 + cc] = z;
        }
    }
    __syncthreads();

    // ---- Phase 1: QKV GEMM (M=64, K=96, N=288), single bf16 MMA ----
    {
        const int wm = warp >> 2, wn = warp & 3;
        const uint32_t aHi = smb + (wm*32 + la15)*208 + kadj*2;
        for (int g = 0; g < 3; ++g) {
            float acc[3][2][4];
            #pragma unroll
            for (int a = 0; a < 3; ++a)
                #pragma unroll
                for (int b = 0; b < 2; ++b)
                    #pragma unroll
                    for (int c = 0; c < 4; ++c) acc[a][b][c] = 0.f;
            #pragma unroll
            for (int s = 0; s < 6; ++s) {
                uint32_t ah[2][4];
                ldsm4(ah[0], aHi + s*32);
                ldsm4(ah[1], aHi + 3328 + s*32);
                #pragma unroll
                for (int nt = 0; nt < 3; ++nt) {
                    int n = wn*72 + g*24 + nt*8 + r;
                    uint2 B = g_Wqh[(s*288 + n)*4 + qd];
                    #pragma unroll
                    for (int mt = 0; mt < 2; ++mt)
                        mma16816(acc[nt][mt], ah[mt], B.x, B.y);
                }
            }
            // epilogue: +bias, route to qHi / kHi / vHi (token-major)
            #pragma unroll
            for (int nt = 0; nt < 3; ++nt) {
                int nb = wn*72 + g*24 + nt*8 + c2;
                float b0v = qkv_b[nb], b1v = qkv_b[nb+1];
                if (nb < 96) { b0v *= QKSCALE; b1v *= QKSCALE; }
                #pragma unroll
                for (int mt = 0; mt < 2; ++mt) {
                    int row = wm*32 + mt*16 + r;
                    float v00 = acc[nt][mt][0] + b0v, v01 = acc[nt][mt][1] + b1v;
                    float v10 = acc[nt][mt][2] + b0v, v11 = acc[nt][mt][3] + b1v;
                    uint32_t* dst;
                    int c;
                    if (nb < 96)       { dst = qh32; c = nb; }
                    else if (nb < 192) { dst = kh32; c = nb - 96; }
                    else               { dst = vh32; c = nb - 192; }
                    dst[(row*104 + c) >> 1]     = packbf(v00, v01);
                    dst[((row+8)*104 + c) >> 1] = packbf(v10, v11);
                }
            }
        }
    }
    __syncthreads();

    // ---- Phase 2+3 fused: scores + bias/mask + softmax + A.V, probs in regs.
    for (int u = warp; u < 12; u += 8) {
        int h = u >> 2, mt = u & 3;
        int rowb = mt * 16;
        uint32_t a[4];
        ldsm4(a, smb + SM_Q + (rowb + la15)*208 + (h*32 + kadj)*2);
        float acc[8][4];
        #pragma unroll
        for (int aa = 0; aa < 8; ++aa)
            #pragma unroll
            for (int c = 0; c < 4; ++c) acc[aa][c] = 0.f;
        const uint32_t kb = smb + SM_K + lbn*208 + (h*32 + kbdj)*2;
        #pragma unroll
        for (int p = 0; p < 4; ++p) {
            uint32_t b[4];
            ldsm4(b, kb + p*16*208);
            mma16816(acc[2*p],   a, b[0], b[1]);
            mma16816(acc[2*p+1], a, b[2], b[3]);
        }
        // bias/mask via 16B vector loads (permuted layout: word p = qd*8+nt)
        const uint32_t* bmb = g_bm2 + ((size_t)(rem*3 + h)) * 2048;
        int i0 = rowb + r, i1 = i0 + 8;
        const uint32_t* p0 = bmb + i0*32 + qd*8;
        const uint32_t* p1 = bmb + i1*32 + qd*8;
        uint4 A0a = ldg_ef_u128(p0), A0b = ldg_ef_u128(p0 + 4);
        uint4 A1a = ldg_ef_u128(p1), A1b = ldg_ef_u128(p1 + 4);
        uint32_t w0[8] = {A0a.x, A0a.y, A0a.z, A0a.w, A0b.x, A0b.y, A0b.z, A0b.w};
        uint32_t w1[8] = {A1a.x, A1a.y, A1a.z, A1a.w, A1b.x, A1b.y, A1b.z, A1b.w};
        float s0 = 0.f, s1 = 0.f;
        #pragma unroll
        for (int nt = 0; nt < 8; ++nt) {
            float2 bm0 = unpack_bf2(w0[nt]);
            float2 bm1 = unpack_bf2(w1[nt]);
            acc[nt][0] = __expf(acc[nt][0] + bm0.x);
            acc[nt][1] = __expf(acc[nt][1] + bm0.y);
            acc[nt][2] = __expf(acc[nt][2] + bm1.x);
            acc[nt][3] = __expf(acc[nt][3] + bm1.y);
            s0 += acc[nt][0] + acc[nt][1];
            s1 += acc[nt][2] + acc[nt][3];
        }
        s0 += __shfl_xor_sync(0xffffffffu, s0, 1);
        s0 += __shfl_xor_sync(0xffffffffu, s0, 2);
        s1 += __shfl_xor_sync(0xffffffffu, s1, 1);
        s1 += __shfl_xor_sync(0xffffffffu, s1, 2);
        float inv0 = 1.0f / s0, inv1 = 1.0f / s1;
        // probs -> bf16 A-fragments directly in registers
        uint32_t pa[4][4];
        #pragma unroll
        for (int ks = 0; ks < 4; ++ks) {
            pa[ks][0] = packbf(acc[2*ks][0]*inv0,   acc[2*ks][1]*inv0);
            pa[ks][1] = packbf(acc[2*ks][2]*inv1,   acc[2*ks][3]*inv1);
            pa[ks][2] = packbf(acc[2*ks+1][0]*inv0, acc[2*ks+1][1]*inv0);
            pa[ks][3] = packbf(acc[2*ks+1][2]*inv1, acc[2*ks+1][3]*inv1);
        }
        // A.V: 16 rows x 32 channels of head h
        float acc3[4][4];
        #pragma unroll
        for (int aa = 0; aa < 4; ++aa)
            #pragma unroll
            for (int c = 0; c < 4; ++c) acc3[aa][c] = 0.f;
        const uint32_t v_b = smb + SM_V + la15*208 + (h*32 + kadj)*2;
        #pragma unroll
        for (int ks = 0; ks < 4; ++ks) {
            uint32_t bh0[4], bh1[4];
            ldsm4t(bh0, v_b + ks*16*208);
            ldsm4t(bh1, v_b + ks*16*208 + 32);
            mma16816(acc3[0], pa[ks], bh0[0], bh0[1]);
            mma16816(acc3[1], pa[ks], bh0[2], bh0[3]);
            mma16816(acc3[2], pa[ks], bh1[0], bh1[1]);
            mma16816(acc3[3], pa[ks], bh1[2], bh1[3]);
        }
        // write ao tile (aliases q; disjoint per unit)
        #pragma unroll
        for (int nt = 0; nt < 4; ++nt) {
            int c = h*32 + nt*8 + c2;
            aoh32[(i0*104 + c) >> 1] = packbf(acc3[nt][0], acc3[nt][1]);
            aoh32[(i1*104 + c) >> 1] = packbf(acc3[nt][2], acc3[nt][3]);
        }
    }
    __syncthreads();

    // ---- Phase 4: proj + bias + residual -> gmem ----
    {
        const int wm = warp >> 2, wn = warp & 3;
        const uint32_t aHi = smb + SM_Q + (wm*32 + la15)*208 + kadj*2;
        float acc[3][2][4];
        #pragma unroll
        for (int a = 0; a < 3; ++a)
            #pragma unroll
            for (int b = 0; b < 2; ++b)
                #pragma unroll
                for (int c = 0; c < 4; ++c) acc[a][b][c] = 0.f;
        #pragma unroll
        for (int s = 0; s < 6; ++s) {
            uint32_t ah[2][4];
            ldsm4(ah[0], aHi + s*32);
            ldsm4(ah[1], aHi + 3328 + s*32);
            #pragma unroll
            for (int nt = 0; nt < 3; ++nt) {
                int n = wn*24 + nt*8 + r;
                uint2 B = g_Wph[(s*96 + n)*4 + qd];
                #pragma unroll
                for (int mt = 0; mt < 2; ++mt)
                    mma16816(acc[nt][mt], ah[mt], B.x, B.y);
            }
        }
        #pragma unroll
        for (int nt = 0; nt < 3; ++nt) {
            int c = wn*24 + nt*8 + c2;
            float2 pb = *(const float2*)(proj_b + c);
            #pragma unroll
            for (int mt = 0; mt < 2; ++mt) {
                int i0 = wm*32 + mt*16 + r;
                if (i0 < NTOK) {
                    size_t base = (size_t)srcI[i0]*96 + c;
                    float2 xr = *(const float2*)(x + base);
                    float2 o;
                    o.x = acc[nt][mt][0] + pb.x + xr.x;
                    o.y = acc[nt][mt][1] + pb.y + xr.y;
                    *(float2*)(out + base) = o;
                }
                int i1 = i0 + 8;
                if (i1 < NTOK) {
                    size_t base = (size_t)srcI[i1]*96 + c;
                    float2 xr = *(const float2*)(x + base);
                    float2 o;
                    o.x = acc[nt][mt][2] + pb.x + xr.x;
                    o.y = acc[nt][mt][3] + pb.y + xr.y;
                    *(float2*)(out + base) = o;
                }
            }
        }
    }
}

// ---------------------------------------------------------------------------
// Kernel 2: LN2 + MLP, 64 tokens/block, 256 threads (8 warps), 2 blocks/SM.
// EXACT R12/R13/R14 version (fast tanh-GELU, uint2 coalesced weights).
// smem: xhi[64][104] @0 (13312), hhi[64][136] @13312 (17408) = 30720 B.
// ---------------------------------------------------------------------------
#define XLDA 104
#define HLDA 136
#define SM2_H 13312
#define SMEM2 30720

__global__ __launch_bounds__(256, 2)
void swin_mlp_mma(const float* __restrict__ g2, const float* __restrict__ b2,
                  const float* __restrict__ fc1_b, const float* __restrict__ fc2_b,
                  float* __restrict__ xio)
{
    extern __shared__ char smem_raw[];
    __nv_bfloat16* xhi = (__nv_bfloat16*)smem_raw;
    uint32_t* hhi32 = (uint32_t*)(smem_raw + SM2_H);

    const uint32_t smb = cvsm(smem_raw);
    const int tid   = threadIdx.x;
    const int warp  = tid >> 5, lane = tid & 31;
    const int tok0  = blockIdx.x * 64;
    const int r     = lane >> 2;
    const int c2    = (lane & 3) * 2;
    const int q     = lane & 3;
    const int nlane = lane >> 2;
    const int la15  = lane & 15;
    const int kadj  = (lane >> 4) << 3;

    // ---- LN2 -> bf16 A matrix in smem ----
    {
        float ga = g2[lane], gb = g2[lane+32], gc = g2[lane+64];
        float ba = b2[lane], bb = b2[lane+32], bc = b2[lane+64];
        for (int t = warp; t < 64; t += 8) {
            const float* xr = xio + (size_t)(tok0+t)*96;
            float v0 = xr[lane], v1 = xr[lane+32], v2 = xr[lane+64];
            float s = v0 + v1 + v2;
            #pragma unroll
            for (int o = 16; o; o >>= 1) s += __shfl_xor_sync(0xffffffffu, s, o);
            float mean = s * (1.0f/96.0f);
            float d0 = v0-mean, d1 = v1-mean, d2 = v2-mean;
            float q2 = d0*d0 + d1*d1 + d2*d2;
            #pragma unroll
            for (int o = 16; o; o >>= 1) q2 += __shfl_xor_sync(0xffffffffu, q2, o);
            float rstd = rsqrtf(q2*(1.0f/96.0f) + 1e-5f);
            xhi[t*XLDA + lane]      = __float2bfloat16_rn(d0*rstd*ga + ba);
            xhi[t*XLDA + lane + 32] = __float2bfloat16_rn(d1*rstd*gb + bb);
            xhi[t*XLDA + lane + 64] = __float2bfloat16_rn(d2*rstd*gc + bc);
        }
    }
    __syncthreads();

    float acc2[6][4];
    #pragma unroll
    for (int i = 0; i < 6; ++i)
        #pragma unroll
        for (int j = 0; j < 4; ++j) acc2[i][j] = 0.f;

    const int wm1 = warp >> 2, wn1 = warp & 3;
    const int wm2 = warp >> 1, wn2 = warp & 1;

    const uint32_t aX = smb + (wm1*32 + la15)*208 + kadj*2;
    const uint32_t aH = smb + SM2_H + (wm2*16 + la15)*272 + kadj*2;

    for (int ch = 0; ch < 3; ++ch) {
        // ---- GEMM1: x(64x96) @ W1[:, ch*128 : +128] ----
        float acc1[2][4][4];
        #pragma unroll
        for (int a = 0; a < 2; ++a)
            #pragma unroll
            for (int b = 0; b < 4; ++b)
                #pragma unroll
                for (int c = 0; c < 4; ++c) acc1[a][b][c] = 0.f;

        #pragma unroll
        for (int s = 0; s < 6; ++s) {
            uint32_t ah[2][4];
            ldsm4(ah[0], aX + s*32);
            ldsm4(ah[1], aX + 3328 + s*32);
            #pragma unroll
            for (int nt = 0; nt < 4; ++nt) {
                int n = ch*128 + wn1*32 + nt*8 + nlane;
                uint2 B = g_W1h[(s*384 + n)*4 + q];
                #pragma unroll
                for (int mt = 0; mt < 2; ++mt)
                    mma16816(acc1[mt][nt], ah[mt], B.x, B.y);
            }
        }

        __syncthreads();   // previous chunk's GEMM2 reads of h are done

        // ---- bias + fast GELU -> h smem (bf16) ----
        #pragma unroll
        for (int mt = 0; mt < 2; ++mt) {
            int row0 = wm1*32 + mt*16 + r;
            #pragma unroll
            for (int nt = 0; nt < 4; ++nt) {
                int cc = wn1*32 + nt*8 + c2;
                float2 bia = *(const float2*)(fc1_b + ch*128 + cc);
                float g00 = gelu_fast(acc1[mt][nt][0] + bia.x);
                float g01 = gelu_fast(acc1[mt][nt][1] + bia.y);
                hhi32[(row0*HLDA + cc) >> 1] = packbf(g00, g01);
                float g10 = gelu_fast(acc1[mt][nt][2] + bia.x);
                float g11 = gelu_fast(acc1[mt][nt][3] + bia.y);
                hhi32[((row0+8)*HLDA + cc) >> 1] = packbf(g10, g11);
            }
        }
        __syncthreads();

        // ---- GEMM2 partial: acc2 += h_chunk(64x128) @ W2[chunk, :] ----
        #pragma unroll
        for (int s = 0; s < 8; ++s) {
            uint32_t ah[4];
            ldsm4(ah, aH + s*32);
            const int S = ch*8 + s;
            #pragma unroll
            for (int nt = 0; nt < 6; ++nt) {
                int n = wn2*48 + nt*8 + nlane;
                uint2 B = g_W2h[(S*96 + n)*4 + q];
                mma16816(acc2[nt], ah, B.x, B.y);
            }
        }
    }

    // ---- epilogue: bias + residual, in place ----
    {
        const int m0 = wm2*16;
        #pragma unroll
        for (int nt = 0; nt < 6; ++nt) {
            int cg = wn2*48 + nt*8 + c2;
            float2 bia = *(const float2*)(fc2_b + cg);
            size_t b0 = (size_t)(tok0 + m0 + r)*96 + cg;
            float2 sk0 = *(const float2*)(xio + b0);
            float2 o0;
            o0.x = acc2[nt][0] + bia.x + sk0.x;
            o0.y = acc2[nt][1] + bia.y + sk0.y;
            *(float2*)(xio + b0) = o0;
            size_t b1 = b0 + (size_t)8*96;
            float2 sk1 = *(const float2*)(xio + b1);
            float2 o1;
            o1.x = acc2[nt][2] + bia.x + sk1.x;
            o1.y = acc2[nt][3] + bia.y + sk1.y;
            *(float2*)(xio + b1) = o1;
        }
    }
}

// ---------------------------------------------------------------------------
extern "C" void kernel_launch(void* const* d_in, const int* in_sizes, int n_in,
                              void* d_out, int out_size)
{
    const float* x      = (const float*)d_in[0];
    const float* g1     = (const float*)d_in[1];
    const float* b1     = (const float*)d_in[2];
    const float* qkv_w  = (const float*)d_in[3];
    const float* qkv_b  = (const float*)d_in[4];
    const float* proj_w = (const float*)d_in[5];
    const float* proj_b = (const float*)d_in[6];
    const float* rpb    = (const float*)d_in[7];
    const float* g2     = (const float*)d_in[8];
    const float* b2     = (const float*)d_in[9];
    const float* fc1_w  = (const float*)d_in[10];
    const float* fc1_b  = (const float*)d_in[11];
    const float* fc2_w  = (const float*)d_in[12];
    const float* fc2_b  = (const float*)d_in[13];
    const int*   relidx = (const int*)d_in[14];
    const float* amask  = (const float*)d_in[15];
    float* out = (float*)d_out;

    cudaFuncSetAttribute(swin_attn_mma, cudaFuncAttributeMaxDynamicSharedMemorySize, SMEM1);
    cudaFuncSetAttribute(swin_mlp_mma,  cudaFuncAttributeMaxDynamicSharedMemorySize, SMEM2);

    pack_weights<<<36, 256>>>(fc1_w, fc2_w, qkv_w, proj_w);
    build_bias_mask<<<3072, 256>>>(rpb, relidx, amask);
    swin_attn_mma<<<NWIN_TOT, 256, SMEM1>>>(x, g1, b1, qkv_b, proj_b, out);
    swin_mlp_mma<<<NBLK2, 256, SMEM2>>>(g2, b2, fc1_b, fc2_b, out);
}